// round 13
// baseline (speedup 1.0000x reference)
#include <cuda_runtime.h>
#include <cuda_bf16.h>
#include <math.h>
#include <stdint.h>

// ---------------------------------------------------------------------------
// Problem constants: N=2048, T=128, IN=64, H=256, 3H=768, NH=2, HD=128, C=30
// ---------------------------------------------------------------------------
#define NB    2048
#define TT    128
#define INDIM 64
#define HH    256
#define G3    768
#define NHD   2
#define HD    128
#define CC    30
#define NTROWS (NB * TT)   // 262144

typedef unsigned long long ull;

// ---------------------------------------------------------------------------
// Device scratch (allocation-free rule: __device__ globals)
// ---------------------------------------------------------------------------
__device__ float g_xw[(size_t)NTROWS * G3];
__device__ float g_ys0[(size_t)NTROWS * HH];
__device__ float g_S[NB * HH];
__device__ float g_wt_w1[HH * HH];
__device__ __nv_bfloat16 g_wih0_h[G3 * INDIM];
__device__ __nv_bfloat16 g_wih0_l[G3 * INDIM];
__device__ __nv_bfloat16 g_wih1_h[G3 * HH];
__device__ __nv_bfloat16 g_wih1_l[G3 * HH];
__device__ __nv_bfloat16 g_whh0_h[G3 * HH];
__device__ __nv_bfloat16 g_whh0_l[G3 * HH];
__device__ __nv_bfloat16 g_whh1_h[G3 * HH];
__device__ __nv_bfloat16 g_whh1_l[G3 * HH];
__device__ float g_qh1[NHD * CC * HD];
__device__ float g_kh1[NHD * NB * HD];
__device__ float g_vh1[NHD * NB * HD];
__device__ float g_B[CC * NHD * HD];
__device__ float g_qh2[NHD * NB * HD];
__device__ float g_kh2[NHD * CC * HD];
__device__ float g_vh2[NHD * CC * HD];
__device__ float g_Sp[NB * HH];
__device__ float g_Smix[NB * HH];
__device__ float g_mlp[NB * HH];
__device__ float g_yraw[NB];

// ---------------------------------------------------------------------------
// Helpers
// ---------------------------------------------------------------------------
__device__ __forceinline__ ull dup2(float a) {
    ull r;
    asm("mov.b64 %0, {%1, %1};" : "=l"(r) : "r"(__float_as_uint(a)));
    return r;
}
__device__ __forceinline__ void ffma2(ull& d, ull a, ull b) {
    asm("fma.rn.f32x2 %0, %1, %2, %0;" : "+l"(d) : "l"(a), "l"(b));
}
__device__ __forceinline__ float2 unpack2(ull v) {
    unsigned lo, hi;
    asm("mov.b64 {%0, %1}, %2;" : "=r"(lo), "=r"(hi) : "l"(v));
    return make_float2(__uint_as_float(lo), __uint_as_float(hi));
}
__device__ __forceinline__ float sigm_f(float x) { return 1.f / (1.f + __expf(-x)); }
__device__ __forceinline__ float tanh_f(float x) {
    float e = __expf(2.f * x);
    return 1.f - 2.f / (e + 1.f);
}
__device__ __forceinline__ uint32_t smem_u32(const void* p) {
    uint32_t a;
    asm("{ .reg .u64 t; cvta.to.shared.u64 t, %1; cvt.u32.u64 %0, t; }"
        : "=r"(a) : "l"(p));
    return a;
}
// mma.sync m16n8k16 row.col bf16 -> f32 (base PTX, works on .target sm_103)
__device__ __forceinline__ void mma_bf16(float* c, const uint32_t* a, const uint32_t* b) {
    asm volatile(
        "mma.sync.aligned.m16n8k16.row.col.f32.bf16.bf16.f32 "
        "{%0,%1,%2,%3}, {%4,%5,%6,%7}, {%8,%9}, {%0,%1,%2,%3};"
        : "+f"(c[0]), "+f"(c[1]), "+f"(c[2]), "+f"(c[3])
        : "r"(a[0]), "r"(a[1]), "r"(a[2]), "r"(a[3]), "r"(b[0]), "r"(b[1]));
}
__device__ __forceinline__ void ldsm_x4(uint32_t* r, uint32_t addr) {
    asm volatile("ldmatrix.sync.aligned.m8n8.x4.shared.b16 {%0,%1,%2,%3}, [%4];"
        : "=r"(r[0]), "=r"(r[1]), "=r"(r[2]), "=r"(r[3]) : "r"(addr));
}
__device__ __forceinline__ void bsplit(float f, unsigned short& h, unsigned short& l) {
    __nv_bfloat16 hb = __float2bfloat16(f);
    __nv_bfloat16 lb = __float2bfloat16(f - __bfloat162float(hb));
    h = *(unsigned short*)&hb;
    l = *(unsigned short*)&lb;
}
#define CPASYNC16(dst, src) \
    asm volatile("cp.async.ca.shared.global [%0], [%1], 16;" \
                 :: "r"(dst), "l"(src))

// ---------------------------------------------------------------------------
// Weight split: w(fp32) -> hi/lo bf16
// ---------------------------------------------------------------------------
__global__ void split_w_kernel(const float* __restrict__ w,
                               __nv_bfloat16* __restrict__ h,
                               __nv_bfloat16* __restrict__ l, int n)
{
    const int i = blockIdx.x * 256 + threadIdx.x;
    if (i < n) {
        const float v = w[i];
        const __nv_bfloat16 hb = __float2bfloat16(v);
        h[i] = hb;
        l[i] = __float2bfloat16(v - __bfloat162float(hb));
    }
}

// ---------------------------------------------------------------------------
// gemm_hmma: C[M,768] = A[M,K](fp32) @ W[768,K]^T(split bf16) + bias.
// BM=128, BN=128, BK=32. 8 warps as 2m x 4n; warp tile 64x32 = 4 m16 x 4 n8.
// Split: AhBh + AlBh + AhBl, fp32 accum. W[n][k] row-major == mma col-major B.
// ---------------------------------------------------------------------------
__global__ __launch_bounds__(256, 2) void gemm_hmma_kernel(
    const float* __restrict__ A,
    const __nv_bfloat16* __restrict__ Wh,
    const __nv_bfloat16* __restrict__ Wl,
    const float* __restrict__ bias,
    float* __restrict__ C,
    int K)
{
    __shared__ __align__(16) unsigned short As_h[128 * 40], As_l[128 * 40];
    __shared__ __align__(16) unsigned short Ws_h[128 * 40], Ws_l[128 * 40];
    const int tid = threadIdx.x;
    const int wid = tid >> 5, lane = tid & 31;
    const int g = lane >> 2, tq = lane & 3;
    const int i4 = lane >> 3, rsub = lane & 7;
    const int wm = wid >> 2, wn = wid & 3;
    const int row0 = blockIdx.y * 128, col0 = blockIdx.x * 128;
    const uint32_t sbAh = smem_u32(As_h), sbAl = smem_u32(As_l);
    const uint32_t sbWh = smem_u32(Ws_h), sbWl = smem_u32(Ws_l);

    float c[4][4][4];
#pragma unroll
    for (int mt = 0; mt < 4; mt++)
#pragma unroll
        for (int nt = 0; nt < 4; nt++)
#pragma unroll
            for (int e = 0; e < 4; e++) c[mt][nt][e] = 0.f;

    // ldmatrix lane offset within a (m16,k16) tile, bytes (row stride 80B)
    const uint32_t aoff = (uint32_t)(((i4 & 1) * 8 + rsub) * 80 + (i4 >> 1) * 16);

    const int nch = K >> 5;
    for (int ch = 0; ch < nch; ch++) {
        __syncthreads();
        // ---- A stage: 128x32 fp32 -> split bf16 smem ----
        {
            const int r = tid >> 1, hs = tid & 1;
            const float* ap = A + (size_t)(row0 + r) * K + ch * 32 + hs * 16;
            unsigned short* dh = As_h + r * 40 + hs * 16;
            unsigned short* dl = As_l + r * 40 + hs * 16;
#pragma unroll
            for (int q = 0; q < 4; q++) {
                const float4 v = *(const float4*)(ap + 4 * q);
                unsigned short h0, l0, h1, l1, h2, l2, h3, l3;
                bsplit(v.x, h0, l0); bsplit(v.y, h1, l1);
                bsplit(v.z, h2, l2); bsplit(v.w, h3, l3);
                *(ull*)(dh + 4 * q) = (ull)h0 | ((ull)h1 << 16) |
                                      ((ull)h2 << 32) | ((ull)h3 << 48);
                *(ull*)(dl + 4 * q) = (ull)l0 | ((ull)l1 << 16) |
                                      ((ull)l2 << 32) | ((ull)l3 << 48);
            }
        }
        // ---- W stage: cp.async 128 rows x 32 b16, hi+lo ----
#pragma unroll
        for (int q = 0; q < 4; q++) {
            const int v = tid + q * 256;        // 0..1023
            const int sp = v >> 9;
            const int u = v & 511;
            const int r = u >> 2, seg = u & 3;
            const __nv_bfloat16* src =
                (sp ? Wl : Wh) + (size_t)(col0 + r) * K + ch * 32 + seg * 8;
            const uint32_t dst = (sp ? sbWl : sbWh) + r * 80 + seg * 16;
            CPASYNC16(dst, src);
        }
        asm volatile("cp.async.commit_group;" ::: "memory");
        asm volatile("cp.async.wait_group 0;" ::: "memory");
        __syncthreads();

        // ---- compute: 2 x k16 ----
#pragma unroll
        for (int s16 = 0; s16 < 2; s16++) {
            uint32_t bh[4][2], bl[4][2];
#pragma unroll
            for (int nt = 0; nt < 4; nt++) {
                const uint32_t ba = (wn * 32 + nt * 8 + g) * 80 + (s16 * 16 + 2 * tq) * 2;
                bh[nt][0] = *(const uint32_t*)((const char*)Ws_h + ba);
                bh[nt][1] = *(const uint32_t*)((const char*)Ws_h + ba + 16);
                bl[nt][0] = *(const uint32_t*)((const char*)Ws_l + ba);
                bl[nt][1] = *(const uint32_t*)((const char*)Ws_l + ba + 16);
            }
#pragma unroll
            for (int mt = 0; mt < 4; mt++) {
                const uint32_t ab = (uint32_t)((wm * 64 + mt * 16) * 80 + s16 * 32) + aoff;
                uint32_t ah[4], al[4];
                ldsm_x4(ah, sbAh + ab);
                ldsm_x4(al, sbAl + ab);
#pragma unroll
                for (int nt = 0; nt < 4; nt++) {
                    mma_bf16(c[mt][nt], ah, bh[nt]);
                    mma_bf16(c[mt][nt], al, bh[nt]);
                    mma_bf16(c[mt][nt], ah, bl[nt]);
                }
            }
        }
    }

    // ---- epilogue ----
#pragma unroll
    for (int nt = 0; nt < 4; nt++) {
        const int col = col0 + wn * 32 + nt * 8 + 2 * tq;
        const float2 bv = *(const float2*)(bias + col);
#pragma unroll
        for (int mt = 0; mt < 4; mt++) {
            const int r1 = row0 + wm * 64 + mt * 16 + g;
            *(float2*)&C[(size_t)r1 * G3 + col] =
                make_float2(c[mt][nt][0] + bv.x, c[mt][nt][1] + bv.y);
            *(float2*)&C[(size_t)(r1 + 8) * G3 + col] =
                make_float2(c[mt][nt][2] + bv.x, c[mt][nt][3] + bv.y);
        }
    }
}

// ---------------------------------------------------------------------------
// Persistent GRU layer on tensor cores. 128 CTAs x 512 threads (16 warps).
// Per step: G^T = Whh (A, streamed k16-chunks, double-buffered) x h^T (B,
// smem bf16 hi/lo) via mma; gate math in fp32 with h carried in registers.
// SMEM: Wbuf 2x49152 | h_hi/h_lo 16x264 b16 | Gt 768x18 f32 | xw 16x776 f32
// ---------------------------------------------------------------------------
#define RBM  16
#define RTHREADS 512
#define WBUF_OFF  0
#define WBUF_HALF 24576            // one split within a buffer
#define WBUF_SZ   49152            // one buffer (hi+lo)
#define H_OFF     98304
#define H_SPLIT   8448             // 16*264*2
#define GT_OFF    115200
#define XW_OFF    170496
#define REC_SMEM  220160           // + 16*776*4 = 49664

__global__ __launch_bounds__(RTHREADS, 1) void gru_rec_kernel(
    const __nv_bfloat16* __restrict__ Wh,   // [768][256]
    const __nv_bfloat16* __restrict__ Wl,   // [768][256]
    const float* __restrict__ bhh,          // [768]
    const float* __restrict__ xw,           // [NTROWS][768], row = n*T + t
    float* __restrict__ ys,                 // [NTROWS][256] or null
    float* __restrict__ hout)               // [NB][256] or null
{
    extern __shared__ char smem[];
    const uint32_t sb = smem_u32(smem);
    unsigned short* h_hi = (unsigned short*)(smem + H_OFF);
    unsigned short* h_lo = (unsigned short*)(smem + H_OFF + H_SPLIT);
    float* Gt   = (float*)(smem + GT_OFF);
    float* xw_s = (float*)(smem + XW_OFF);

    const int tid = threadIdx.x;
    const int n0 = blockIdx.x * RBM;
    const int w = tid >> 5, lane = tid & 31;
    const int g = lane >> 2, tq = lane & 3;
    const int i4 = lane >> 3, rsub = lane & 7;
    // gate mapping: row qm (0..15), cols qj..qj+7
    const int qm = tid >> 5;
    const int qj = (lane) << 3;

    // ldmatrix lane offset within a (16n,16k) W tile: rows 32B
    const uint32_t aoff = (uint32_t)(((i4 & 1) * 8 + rsub) * 32 + (i4 >> 1) * 16);

    // bias regs for this warp's 3 n16 tiles
    float bb[3][2];
#pragma unroll
    for (int i = 0; i < 3; i++) {
        bb[i][0] = bhh[w * 48 + i * 16 + g];
        bb[i][1] = bhh[w * 48 + i * 16 + 8 + g];
    }

    // zero h splits; h fp32 in registers
    for (int i = tid; i < 16 * 264; i += RTHREADS) { h_hi[i] = 0; h_lo[i] = 0; }
    float hreg[8];
#pragma unroll
    for (int j = 0; j < 8; j++) hreg[j] = 0.f;
    __syncthreads();

    for (int t = 0; t < TT; t++) {
        // ---- group 1: xw(t) prefetch (16 rows x 192 float4) ----
#pragma unroll
        for (int q = 0; q < 6; q++) {
            const int v = tid + q * RTHREADS;
            const int rm = v / 192;
            const int c4 = v - rm * 192;
            const float* src = xw + ((size_t)(n0 + rm) * TT + t) * G3 + c4 * 4;
            CPASYNC16(sb + XW_OFF + rm * 3104 + c4 * 16, src);
        }
        asm volatile("cp.async.commit_group;" ::: "memory");
        // ---- groups 2,3: W chunks 0,1 -> buffers 0,1 ----
#pragma unroll
        for (int pc = 0; pc < 2; pc++) {
#pragma unroll
            for (int q = 0; q < 6; q++) {
                const int v = tid + q * RTHREADS;       // 0..3071
                const int sp = v / 1536;
                const int u = v - sp * 1536;
                const int r = u >> 1, seg = u & 1;
                const __nv_bfloat16* src =
                    (sp ? Wl : Wh) + (size_t)r * HH + pc * 16 + seg * 8;
                CPASYNC16(sb + WBUF_OFF + pc * WBUF_SZ + sp * WBUF_HALF +
                          r * 32 + seg * 16, src);
            }
            asm volatile("cp.async.commit_group;" ::: "memory");
        }

        float c[3][2][4];
#pragma unroll
        for (int i = 0; i < 3; i++)
#pragma unroll
            for (int nb = 0; nb < 2; nb++)
#pragma unroll
                for (int e = 0; e < 4; e++) c[i][nb][e] = 0.f;

        for (int kc = 0; kc < 16; kc++) {
            if (kc < 15) asm volatile("cp.async.wait_group 1;" ::: "memory");
            else         asm volatile("cp.async.wait_group 0;" ::: "memory");
            __syncthreads();

            // B (h) frags for this k16
            uint32_t bh[2][2], bl[2][2];
#pragma unroll
            for (int nb = 0; nb < 2; nb++) {
                const uint32_t ba = (nb * 8 + g) * 528 + kc * 32 + tq * 4;
                bh[nb][0] = *(const uint32_t*)((const char*)h_hi + ba);
                bh[nb][1] = *(const uint32_t*)((const char*)h_hi + ba + 16);
                bl[nb][0] = *(const uint32_t*)((const char*)h_lo + ba);
                bl[nb][1] = *(const uint32_t*)((const char*)h_lo + ba + 16);
            }
            const uint32_t wb = sb + WBUF_OFF + (kc & 1) * WBUF_SZ;
#pragma unroll
            for (int i = 0; i < 3; i++) {
                const uint32_t tb = (uint32_t)((w * 48 + i * 16) * 32) + aoff;
                uint32_t ah[4], al[4];
                ldsm_x4(ah, wb + tb);
                ldsm_x4(al, wb + WBUF_HALF + tb);
#pragma unroll
                for (int nb = 0; nb < 2; nb++) {
                    mma_bf16(c[i][nb], ah, bh[nb]);
                    mma_bf16(c[i][nb], al, bh[nb]);
                    mma_bf16(c[i][nb], ah, bl[nb]);
                }
            }
            __syncthreads();
            if (kc + 2 < 16) {                 // refill the buffer just drained
#pragma unroll
                for (int q = 0; q < 6; q++) {
                    const int v = tid + q * RTHREADS;
                    const int sp = v / 1536;
                    const int u = v - sp * 1536;
                    const int r = u >> 1, seg = u & 1;
                    const __nv_bfloat16* src =
                        (sp ? Wl : Wh) + (size_t)r * HH + (kc + 2) * 16 + seg * 8;
                    CPASYNC16(sb + WBUF_OFF + (kc & 1) * WBUF_SZ + sp * WBUF_HALF +
                              r * 32 + seg * 16, src);
                }
                asm volatile("cp.async.commit_group;" ::: "memory");
            }
        }

        // ---- store G^T (+bias) ----
#pragma unroll
        for (int i = 0; i < 3; i++) {
            const int nr = w * 48 + i * 16 + g;
#pragma unroll
            for (int nb = 0; nb < 2; nb++) {
                const int mc = nb * 8 + 2 * tq;
                *(float2*)&Gt[nr * 18 + mc] =
                    make_float2(c[i][nb][0] + bb[i][0], c[i][nb][1] + bb[i][0]);
                *(float2*)&Gt[(nr + 8) * 18 + mc] =
                    make_float2(c[i][nb][2] + bb[i][1], c[i][nb][3] + bb[i][1]);
            }
        }
        __syncthreads();

        // ---- gate update (fp32, h in registers) ----
        {
            const float* xr = xw_s + qm * 776;
            unsigned short hh[8], hl[8];
            float hn[8];
#pragma unroll
            for (int j = 0; j < 8; j++) {
                const int jj = qj + j;
                const float r = sigm_f(xr[jj] + Gt[jj * 18 + qm]);
                const float z = sigm_f(xr[256 + jj] + Gt[(256 + jj) * 18 + qm]);
                const float nv = tanh_f(xr[512 + jj] + r * Gt[(512 + jj) * 18 + qm]);
                hn[j] = (1.f - z) * nv + z * hreg[j];
                hreg[j] = hn[j];
                bsplit(hn[j], hh[j], hl[j]);
            }
            const uint32_t hb = qm * 528 + qj * 2;   // byte offset
#pragma unroll
            for (int q = 0; q < 2; q++) {
                *(ull*)((char*)h_hi + hb + 8 * q) =
                    (ull)hh[4 * q] | ((ull)hh[4 * q + 1] << 16) |
                    ((ull)hh[4 * q + 2] << 32) | ((ull)hh[4 * q + 3] << 48);
                *(ull*)((char*)h_lo + hb + 8 * q) =
                    (ull)hl[4 * q] | ((ull)hl[4 * q + 1] << 16) |
                    ((ull)hl[4 * q + 2] << 32) | ((ull)hl[4 * q + 3] << 48);
            }
            if (ys) {
                float4* dst = (float4*)(ys + ((size_t)(n0 + qm) * TT + t) * HH + qj);
                dst[0] = make_float4(hn[0], hn[1], hn[2], hn[3]);
                dst[1] = make_float4(hn[4], hn[5], hn[6], hn[7]);
            }
        }
        __syncthreads();
    }

    if (hout) {
        float* dst = hout + (size_t)(n0 + qm) * HH + qj;
        *(float4*)(dst)     = make_float4(hreg[0], hreg[1], hreg[2], hreg[3]);
        *(float4*)(dst + 4) = make_float4(hreg[4], hreg[5], hreg[6], hreg[7]);
    }
}

// ---------------------------------------------------------------------------
// Transpose (for W1 / MLP gemm2 only)
// ---------------------------------------------------------------------------
__global__ void transpose_kernel(const float* __restrict__ in,
                                 float* __restrict__ out, int R, int C)
{
    __shared__ float t[32][33];
    const int c0 = blockIdx.x * 32, r0 = blockIdx.y * 32;
    for (int j = threadIdx.y; j < 32; j += 8)
        t[j][threadIdx.x] = in[(size_t)(r0 + j) * C + c0 + threadIdx.x];
    __syncthreads();
    for (int j = threadIdx.y; j < 32; j += 8)
        out[(size_t)(c0 + j) * R + r0 + threadIdx.x] = t[threadIdx.x][j];
}

// ---------------------------------------------------------------------------
// gemm2 (fp32 f32x2) — MLP GEMM only.
// ---------------------------------------------------------------------------
#define S2 258

__global__ __launch_bounds__(256, 2) void gemm2_kernel(
    const float* __restrict__ A,
    const float* __restrict__ Wt,
    const float* __restrict__ bias,
    float* __restrict__ C,
    int M, int Nn, int K)
{
    __shared__ float AsD[16 * S2];
    __shared__ float Ws[16 * 128];
    const int tid = threadIdx.x;
    const int row0 = blockIdx.y * 128;
    const int col0 = blockIdx.x * 128;
    const int ngrp = tid & 15, mgrp = tid >> 4;
    const int m0 = mgrp * 8;
    const int nc0 = 2 * ngrp;

    ull acc[8][4];
#pragma unroll
    for (int i = 0; i < 8; i++)
#pragma unroll
        for (int p = 0; p < 4; p++) acc[i][p] = 0ULL;

    for (int k0 = 0; k0 < K; k0 += 16) {
#pragma unroll
        for (int q = 0; q < 2; q++) {
            const int v = tid + q * 256;
            const int rm = v >> 2, kc = (v & 3) << 2;
            float4 av = *(const float4*)(A + (size_t)(row0 + rm) * K + k0 + kc);
            *(ull*)&AsD[(kc + 0) * S2 + 2 * rm] = dup2(av.x);
            *(ull*)&AsD[(kc + 1) * S2 + 2 * rm] = dup2(av.y);
            *(ull*)&AsD[(kc + 2) * S2 + 2 * rm] = dup2(av.z);
            *(ull*)&AsD[(kc + 3) * S2 + 2 * rm] = dup2(av.w);
            const int rk = v >> 5, nc = (v & 31) << 2;
            *(float4*)&Ws[rk * 128 + nc] =
                *(const float4*)(Wt + (size_t)(k0 + rk) * Nn + col0 + nc);
        }
        __syncthreads();
#pragma unroll
        for (int k = 0; k < 16; k++) {
            ull w[4];
#pragma unroll
            for (int p = 0; p < 4; p++)
                w[p] = *(const ull*)&Ws[k * 128 + nc0 + 32 * p];
#pragma unroll
            for (int i = 0; i < 8; i++) {
                ull ad = *(const ull*)&AsD[k * S2 + 2 * (m0 + i)];
#pragma unroll
                for (int p = 0; p < 4; p++) ffma2(acc[i][p], w[p], ad);
            }
        }
        __syncthreads();
    }

    float2 bp[4];
#pragma unroll
    for (int p = 0; p < 4; p++)
        bp[p] = *(const float2*)(bias + col0 + nc0 + 32 * p);
#pragma unroll
    for (int i = 0; i < 8; i++) {
        float* crow = C + (size_t)(row0 + m0 + i) * Nn + col0;
#pragma unroll
        for (int p = 0; p < 4; p++) {
            float2 v = unpack2(acc[i][p]);
            *(float2*)(crow + nc0 + 32 * p) =
                make_float2(v.x + bp[p].x, v.y + bp[p].y);
        }
    }
}

// ---------------------------------------------------------------------------
// Attention / tail kernels (unchanged)
// ---------------------------------------------------------------------------
__global__ void proj_kernel(const float* __restrict__ A, int M,
                            const float* __restrict__ Wm,
                            const float* __restrict__ bias,
                            float* __restrict__ out)
{
    const int head = blockIdx.z;
    const int col = blockIdx.x * 16 + threadIdx.x;
    const int row = blockIdx.y * 16 + threadIdx.y;
    const int rc = min(row, M - 1);
    const float* W = Wm + (size_t)head * HH * HD;
    __shared__ float As[16][17], Wsh[16][17];
    float acc = 0.f;
    for (int k0 = 0; k0 < HH; k0 += 16) {
        As[threadIdx.y][threadIdx.x] = A[(size_t)rc * HH + k0 + threadIdx.x];
        Wsh[threadIdx.y][threadIdx.x] = W[(size_t)(k0 + threadIdx.y) * HD + col];
        __syncthreads();
#pragma unroll
        for (int k = 0; k < 16; k++)
            acc += As[threadIdx.y][k] * Wsh[k][threadIdx.x];
        __syncthreads();
    }
    if (row < M)
        out[((size_t)head * M + row) * HD + col] = acc + bias[head * HD + col];
}

__global__ void attn1_kernel(const float* __restrict__ qh,
                             const float* __restrict__ kh,
                             const float* __restrict__ vh,
                             float* __restrict__ B)
{
    const int head = blockIdx.x / CC;
    const int l = blockIdx.x % CC;
    const int tid = threadIdx.x;
    __shared__ float p[NB];
    __shared__ float q[HD];
    __shared__ float red[256];
    if (tid < HD) q[tid] = qh[((size_t)head * CC + l) * HD + tid];
    __syncthreads();
    const float scale = 0.08838834764831845f;
    float lmax = -1e30f;
    for (int k = tid; k < NB; k += 256) {
        const float* kr = kh + ((size_t)head * NB + k) * HD;
        float s = 0.f;
#pragma unroll 4
        for (int d = 0; d < HD; d++) s += q[d] * kr[d];
        s *= scale;
        p[k] = s;
        lmax = fmaxf(lmax, s);
    }
    red[tid] = lmax; __syncthreads();
    for (int s = 128; s > 0; s >>= 1) {
        if (tid < s) red[tid] = fmaxf(red[tid], red[tid + s]);
        __syncthreads();
    }
    const float m = red[0];
    __syncthreads();
    float lsum = 0.f;
    for (int k = tid; k < NB; k += 256) {
        const float e = expf(p[k] - m);
        p[k] = e;
        lsum += e;
    }
    red[tid] = lsum; __syncthreads();
    for (int s = 128; s > 0; s >>= 1) {
        if (tid < s) red[tid] += red[tid + s];
        __syncthreads();
    }
    const float inv = 1.f / red[0];
    __syncthreads();
    const int col = tid & 127;
    const int half = tid >> 7;
    float o = 0.f;
    for (int k = half * 1024; k < half * 1024 + 1024; k++)
        o += p[k] * vh[((size_t)head * NB + k) * HD + col];
    red[tid] = o; __syncthreads();
    if (tid < HD)
        B[l * (NHD * HD) + head * HD + tid] = (red[tid] + red[tid + 128]) * inv;
}

__global__ void attn2_kernel(const float* __restrict__ qh,
                             const float* __restrict__ kh,
                             const float* __restrict__ vh,
                             float* __restrict__ Sp)
{
    const int l = blockIdx.x;
    const int head = blockIdx.y;
    const int tid = threadIdx.x;
    __shared__ float q[HD];
    __shared__ float sc[CC];
    q[tid] = qh[((size_t)head * NB + l) * HD + tid];
    __syncthreads();
    const float scale = 0.08838834764831845f;
    if (tid < CC) {
        const float* kr = kh + (head * CC + tid) * HD;
        float s = 0.f;
        for (int d = 0; d < HD; d++) s += q[d] * kr[d];
        sc[tid] = s * scale;
    }
    __syncthreads();
    float m = -1e30f;
#pragma unroll
    for (int k = 0; k < CC; k++) m = fmaxf(m, sc[k]);
    float sum = 0.f, o = 0.f;
#pragma unroll
    for (int k = 0; k < CC; k++) {
        const float e = expf(sc[k] - m);
        sum += e;
        o += e * vh[(head * CC + k) * HD + tid];
    }
    Sp[(size_t)l * HH + head * HD + tid] = o / sum;
}

__global__ void gate_mix_kernel(const float* __restrict__ S,
                                const float* __restrict__ Sp,
                                const float* __restrict__ Wg,
                                const float* __restrict__ bg,
                                float* __restrict__ Smix)
{
    __shared__ float red[256];
    const int l = blockIdx.x, d = threadIdx.x;
    const float sv = S[(size_t)l * HH + d];
    red[d] = sv * Wg[d];
    __syncthreads();
    for (int s = 128; s > 0; s >>= 1) {
        if (d < s) red[d] += red[d + s];
        __syncthreads();
    }
    const float alpha = 1.f / (1.f + expf(-(red[0] + bg[0])));
    Smix[(size_t)l * HH + d] = alpha * Sp[(size_t)l * HH + d] + (1.f - alpha) * sv;
}

__global__ void relu_add_kernel(const float* __restrict__ mlp,
                                float* __restrict__ Smix)
{
    const int idx = blockIdx.x * blockDim.x + threadIdx.x;
    Smix[idx] += fmaxf(mlp[idx], 0.f);
}

__global__ void rowdot_kernel(const float* __restrict__ S,
                              const float* __restrict__ W2,
                              const float* __restrict__ b2,
                              float* __restrict__ y)
{
    __shared__ float red[256];
    const int l = blockIdx.x, tid = threadIdx.x;
    red[tid] = S[(size_t)l * HH + tid] * W2[tid];
    __syncthreads();
    for (int s = 128; s > 0; s >>= 1) {
        if (tid < s) red[tid] += red[tid + s];
        __syncthreads();
    }
    if (tid == 0) y[l] = red[0] + b2[0];
}

__global__ void normalize_kernel(const float* __restrict__ y,
                                 float* __restrict__ out)
{
    __shared__ float red[1024];
    const int tid = threadIdx.x;
    const float a = y[tid], b = y[tid + 1024];
    red[tid] = a + b; __syncthreads();
    for (int s = 512; s > 0; s >>= 1) {
        if (tid < s) red[tid] += red[tid + s];
        __syncthreads();
    }
    const float mean = red[0] * (1.f / 2048.f);
    __syncthreads();
    const float da = a - mean, db = b - mean;
    red[tid] = da * da + db * db; __syncthreads();
    for (int s = 512; s > 0; s >>= 1) {
        if (tid < s) red[tid] += red[tid + s];
        __syncthreads();
    }
    const float inv = 1.f / (sqrtf(red[0] / 2047.f) + 1e-8f);
    out[tid] = da * inv;
    out[tid + 1024] = db * inv;
}

// ---------------------------------------------------------------------------
// Host driver — default stream, graph-capturable.
// ---------------------------------------------------------------------------
extern "C" void kernel_launch(void* const* d_in, const int* in_sizes, int n_in,
                              void* d_out, int out_size)
{
    const float* x      = (const float*)d_in[0];
    const float* W_ih0  = (const float*)d_in[1];
    const float* W_hh0  = (const float*)d_in[2];
    const float* b_ih0  = (const float*)d_in[3];
    const float* b_hh0  = (const float*)d_in[4];
    const float* W_ih1  = (const float*)d_in[5];
    const float* W_hh1  = (const float*)d_in[6];
    const float* b_ih1  = (const float*)d_in[7];
    const float* b_hh1  = (const float*)d_in[8];
    const float* Wq     = (const float*)d_in[9];
    const float* bq     = (const float*)d_in[10];
    const float* Wk     = (const float*)d_in[11];
    const float* bk     = (const float*)d_in[12];
    const float* Wv     = (const float*)d_in[13];
    const float* bv     = (const float*)d_in[14];
    const float* R      = (const float*)d_in[15];
    const float* W_gate = (const float*)d_in[16];
    const float* b_gate = (const float*)d_in[17];
    const float* W1     = (const float*)d_in[18];
    const float* b1     = (const float*)d_in[19];
    const float* W2     = (const float*)d_in[20];
    const float* b2     = (const float*)d_in[21];
    float* out = (float*)d_out;

    float *xw, *ys0, *S, *wt_w1;
    __nv_bfloat16 *wih0_h, *wih0_l, *wih1_h, *wih1_l;
    __nv_bfloat16 *whh0_h, *whh0_l, *whh1_h, *whh1_l;
    float *qh1, *kh1, *vh1, *Bb, *qh2, *kh2, *vh2, *Sp, *Smix, *mlp, *yraw;
    cudaGetSymbolAddress((void**)&xw, g_xw);
    cudaGetSymbolAddress((void**)&ys0, g_ys0);
    cudaGetSymbolAddress((void**)&S, g_S);
    cudaGetSymbolAddress((void**)&wt_w1, g_wt_w1);
    cudaGetSymbolAddress((void**)&wih0_h, g_wih0_h);
    cudaGetSymbolAddress((void**)&wih0_l, g_wih0_l);
    cudaGetSymbolAddress((void**)&wih1_h, g_wih1_h);
    cudaGetSymbolAddress((void**)&wih1_l, g_wih1_l);
    cudaGetSymbolAddress((void**)&whh0_h, g_whh0_h);
    cudaGetSymbolAddress((void**)&whh0_l, g_whh0_l);
    cudaGetSymbolAddress((void**)&whh1_h, g_whh1_h);
    cudaGetSymbolAddress((void**)&whh1_l, g_whh1_l);
    cudaGetSymbolAddress((void**)&qh1, g_qh1);
    cudaGetSymbolAddress((void**)&kh1, g_kh1);
    cudaGetSymbolAddress((void**)&vh1, g_vh1);
    cudaGetSymbolAddress((void**)&Bb, g_B);
    cudaGetSymbolAddress((void**)&qh2, g_qh2);
    cudaGetSymbolAddress((void**)&kh2, g_kh2);
    cudaGetSymbolAddress((void**)&vh2, g_vh2);
    cudaGetSymbolAddress((void**)&Sp, g_Sp);
    cudaGetSymbolAddress((void**)&Smix, g_Smix);
    cudaGetSymbolAddress((void**)&mlp, g_mlp);
    cudaGetSymbolAddress((void**)&yraw, g_yraw);

    cudaFuncSetAttribute(gru_rec_kernel,
                         cudaFuncAttributeMaxDynamicSharedMemorySize, REC_SMEM);

    const dim3 blk2(16, 16);
    const dim3 tb(32, 8);

    // 0-3: weight splits
    split_w_kernel<<<(G3 * HH + 255) / 256, 256>>>(W_hh0, whh0_h, whh0_l, G3 * HH);
    split_w_kernel<<<(G3 * HH + 255) / 256, 256>>>(W_hh1, whh1_h, whh1_l, G3 * HH);
    split_w_kernel<<<(G3 * INDIM + 255) / 256, 256>>>(W_ih0, wih0_h, wih0_l, G3 * INDIM);
    split_w_kernel<<<(G3 * HH + 255) / 256, 256>>>(W_ih1, wih1_h, wih1_l, G3 * HH);

    // 4: xW0 (HMMA), 5: rec0 (ncu -s 5 captures this)
    gemm_hmma_kernel<<<dim3(G3 / 128, NTROWS / 128), 256>>>(
        x, wih0_h, wih0_l, b_ih0, xw, INDIM);
    gru_rec_kernel<<<NB / RBM, RTHREADS, REC_SMEM>>>(
        whh0_h, whh0_l, b_hh0, xw, ys0, nullptr);

    // 6: xW1, 7: rec1
    gemm_hmma_kernel<<<dim3(G3 / 128, NTROWS / 128), 256>>>(
        ys0, wih1_h, wih1_l, b_ih1, xw, HH);
    gru_rec_kernel<<<NB / RBM, RTHREADS, REC_SMEM>>>(
        whh1_h, whh1_l, b_hh1, xw, nullptr, S);

    // MLP weight transpose (fp32 path)
    transpose_kernel<<<dim3(HH / 32, HH / 32), tb>>>(W1, wt_w1, HH, HH);

    // Attention: B = MHA(R, S, S), S' = MHA(S, B, B)
    proj_kernel<<<dim3(8, 2, NHD), blk2>>>(R, CC, Wq, bq, qh1);
    proj_kernel<<<dim3(8, NB / 16, NHD), blk2>>>(S, NB, Wk, bk, kh1);
    proj_kernel<<<dim3(8, NB / 16, NHD), blk2>>>(S, NB, Wv, bv, vh1);
    attn1_kernel<<<NHD * CC, 256>>>(qh1, kh1, vh1, Bb);
    proj_kernel<<<dim3(8, NB / 16, NHD), blk2>>>(S, NB, Wq, bq, qh2);
    proj_kernel<<<dim3(8, 2, NHD), blk2>>>(Bb, CC, Wk, bk, kh2);
    proj_kernel<<<dim3(8, 2, NHD), blk2>>>(Bb, CC, Wv, bv, vh2);
    attn2_kernel<<<dim3(NB, NHD), 128>>>(qh2, kh2, vh2, Sp);

    // Gate mix + MLP + output
    gate_mix_kernel<<<NB, 256>>>(S, Sp, W_gate, b_gate, Smix);
    gemm2_kernel<<<dim3(HH / 128, NB / 128), 256>>>(
        Smix, wt_w1, b1, mlp, NB, HH, HH);
    relu_add_kernel<<<(NB * HH) / 256, 256>>>(mlp, Smix);
    rowdot_kernel<<<NB, 256>>>(Smix, W2, b2, yraw);
    normalize_kernel<<<1, 1024>>>(yraw, out);
}

// round 14
// speedup vs baseline: 1.2868x; 1.2868x over previous
#include <cuda_runtime.h>
#include <cuda_bf16.h>
#include <math.h>
#include <stdint.h>

// ---------------------------------------------------------------------------
// Problem constants: N=2048, T=128, IN=64, H=256, 3H=768, NH=2, HD=128, C=30
// ---------------------------------------------------------------------------
#define NB    2048
#define TT    128
#define INDIM 64
#define HH    256
#define G3    768
#define NHD   2
#define HD    128
#define CC    30
#define NTROWS (NB * TT)   // 262144

typedef unsigned long long ull;

// ---------------------------------------------------------------------------
// Device scratch (allocation-free rule: __device__ globals)
// ---------------------------------------------------------------------------
__device__ float g_xw[(size_t)NTROWS * G3];
__device__ float g_ys0[(size_t)NTROWS * HH];
__device__ float g_S[NB * HH];
__device__ float g_wt_hh0[HH * G3];           // W_hh0^T (fp32, rec)
__device__ float g_wt_hh1[HH * G3];           // W_hh1^T (fp32, rec)
__device__ float g_wt_w1[HH * HH];
__device__ __nv_bfloat16 g_wih0_h[G3 * INDIM];
__device__ __nv_bfloat16 g_wih0_l[G3 * INDIM];
__device__ __nv_bfloat16 g_wih1_h[G3 * HH];
__device__ __nv_bfloat16 g_wih1_l[G3 * HH];
__device__ float g_wqkv[6 * HH * HD];         // packed [q0,q1,k0,k1,v0,v1]
__device__ float g_bqkv[6 * HD];
__device__ float g_qkv[6 * NB * HD];          // combined projection output
__device__ float g_qh1[NHD * CC * HD];
__device__ float g_B[CC * NHD * HD];
__device__ float g_kh2[NHD * CC * HD];
__device__ float g_vh2[NHD * CC * HD];
__device__ float g_Sp[NB * HH];
__device__ float g_Smix[NB * HH];
__device__ float g_mlp[NB * HH];
__device__ float g_yraw[NB];

// ---------------------------------------------------------------------------
// Helpers
// ---------------------------------------------------------------------------
__device__ __forceinline__ ull dup2(float a) {
    ull r;
    asm("mov.b64 %0, {%1, %1};" : "=l"(r) : "r"(__float_as_uint(a)));
    return r;
}
__device__ __forceinline__ void ffma2(ull& d, ull a, ull b) {
    asm("fma.rn.f32x2 %0, %1, %2, %0;" : "+l"(d) : "l"(a), "l"(b));
}
__device__ __forceinline__ float2 unpack2(ull v) {
    unsigned lo, hi;
    asm("mov.b64 {%0, %1}, %2;" : "=r"(lo), "=r"(hi) : "l"(v));
    return make_float2(__uint_as_float(lo), __uint_as_float(hi));
}
__device__ __forceinline__ float sigm_f(float x) { return 1.f / (1.f + __expf(-x)); }
__device__ __forceinline__ float tanh_f(float x) {
    float e = __expf(2.f * x);
    return 1.f - 2.f / (e + 1.f);
}
__device__ __forceinline__ uint32_t smem_u32(const void* p) {
    uint32_t a;
    asm("{ .reg .u64 t; cvta.to.shared.u64 t, %1; cvt.u32.u64 %0, t; }"
        : "=r"(a) : "l"(p));
    return a;
}
// mma.sync m16n8k16 row.col bf16 -> f32 (base PTX; valid on .target sm_103)
__device__ __forceinline__ void mma_bf16(float* c, const uint32_t* a, const uint32_t* b) {
    asm volatile(
        "mma.sync.aligned.m16n8k16.row.col.f32.bf16.bf16.f32 "
        "{%0,%1,%2,%3}, {%4,%5,%6,%7}, {%8,%9}, {%0,%1,%2,%3};"
        : "+f"(c[0]), "+f"(c[1]), "+f"(c[2]), "+f"(c[3])
        : "r"(a[0]), "r"(a[1]), "r"(a[2]), "r"(a[3]), "r"(b[0]), "r"(b[1]));
}
__device__ __forceinline__ void ldsm_x4(uint32_t* r, uint32_t addr) {
    asm volatile("ldmatrix.sync.aligned.m8n8.x4.shared.b16 {%0,%1,%2,%3}, [%4];"
        : "=r"(r[0]), "=r"(r[1]), "=r"(r[2]), "=r"(r[3]) : "r"(addr));
}
__device__ __forceinline__ void bsplit(float f, unsigned short& h, unsigned short& l) {
    __nv_bfloat16 hb = __float2bfloat16(f);
    __nv_bfloat16 lb = __float2bfloat16(f - __bfloat162float(hb));
    h = *(unsigned short*)&hb;
    l = *(unsigned short*)&lb;
}
#define CPASYNC16(dst, src) \
    asm volatile("cp.async.ca.shared.global [%0], [%1], 16;" \
                 :: "r"(dst), "l"(src))

// ---------------------------------------------------------------------------
// Weight split: w(fp32) -> hi/lo bf16
// ---------------------------------------------------------------------------
__global__ void split_w_kernel(const float* __restrict__ w,
                               __nv_bfloat16* __restrict__ h,
                               __nv_bfloat16* __restrict__ l, int n)
{
    const int i = blockIdx.x * 256 + threadIdx.x;
    if (i < n) {
        const float v = w[i];
        const __nv_bfloat16 hb = __float2bfloat16(v);
        h[i] = hb;
        l[i] = __float2bfloat16(v - __bfloat162float(hb));
    }
}

// ---------------------------------------------------------------------------
// Pack Wq/Wk/Wv ([NH][HH][HD] each) -> wqkv[6][HH][HD], slot = mat*2+head.
// ---------------------------------------------------------------------------
__global__ void pack_qkv_kernel(const float* __restrict__ Wq,
                                const float* __restrict__ Wk,
                                const float* __restrict__ Wv,
                                const float* __restrict__ bq,
                                const float* __restrict__ bk,
                                const float* __restrict__ bv,
                                float* __restrict__ wqkv,
                                float* __restrict__ bqkv)
{
    const int i = blockIdx.x * 256 + threadIdx.x;
    const int HW = NHD * HH * HD;      // one matrix set
    if (i < 6 * HH * HD) {
        const int s = i / (HH * HD);
        const int mat = s >> 1, head = s & 1;
        const int rest = i - s * (HH * HD);
        const float* src = (mat == 0) ? Wq : (mat == 1) ? Wk : Wv;
        wqkv[i] = src[head * HH * HD + rest];
        (void)HW;
    }
    if (i < 6 * HD) {
        const int s = i / HD, c = i % HD;
        const int mat = s >> 1, head = s & 1;
        const float* src = (mat == 0) ? bq : (mat == 1) ? bk : bv;
        bqkv[i] = src[head * HD + c];
    }
}

// ---------------------------------------------------------------------------
// gemm_hmma: C[M,768] = A[M,K](fp32) @ W[768,K]^T(split bf16) + bias.
// BM=128, BN=128, BK=32; 8 warps 2m x 4n; AhBh + AlBh + AhBl, fp32 accum.
// (validated R13: rel_err 7e-6)
// ---------------------------------------------------------------------------
__global__ __launch_bounds__(256, 2) void gemm_hmma_kernel(
    const float* __restrict__ A,
    const __nv_bfloat16* __restrict__ Wh,
    const __nv_bfloat16* __restrict__ Wl,
    const float* __restrict__ bias,
    float* __restrict__ C,
    int K)
{
    __shared__ __align__(16) unsigned short As_h[128 * 40], As_l[128 * 40];
    __shared__ __align__(16) unsigned short Ws_h[128 * 40], Ws_l[128 * 40];
    const int tid = threadIdx.x;
    const int wid = tid >> 5, lane = tid & 31;
    const int g = lane >> 2, tq = lane & 3;
    const int i4 = lane >> 3, rsub = lane & 7;
    const int wm = wid >> 2, wn = wid & 3;
    const int row0 = blockIdx.y * 128, col0 = blockIdx.x * 128;
    const uint32_t sbAh = smem_u32(As_h), sbAl = smem_u32(As_l);
    const uint32_t sbWh = smem_u32(Ws_h), sbWl = smem_u32(Ws_l);

    float c[4][4][4];
#pragma unroll
    for (int mt = 0; mt < 4; mt++)
#pragma unroll
        for (int nt = 0; nt < 4; nt++)
#pragma unroll
            for (int e = 0; e < 4; e++) c[mt][nt][e] = 0.f;

    const uint32_t aoff = (uint32_t)(((i4 & 1) * 8 + rsub) * 80 + (i4 >> 1) * 16);

    const int nch = K >> 5;
    for (int ch = 0; ch < nch; ch++) {
        __syncthreads();
        {
            const int r = tid >> 1, hs = tid & 1;
            const float* ap = A + (size_t)(row0 + r) * K + ch * 32 + hs * 16;
            unsigned short* dh = As_h + r * 40 + hs * 16;
            unsigned short* dl = As_l + r * 40 + hs * 16;
#pragma unroll
            for (int q = 0; q < 4; q++) {
                const float4 v = *(const float4*)(ap + 4 * q);
                unsigned short h0, l0, h1, l1, h2, l2, h3, l3;
                bsplit(v.x, h0, l0); bsplit(v.y, h1, l1);
                bsplit(v.z, h2, l2); bsplit(v.w, h3, l3);
                *(ull*)(dh + 4 * q) = (ull)h0 | ((ull)h1 << 16) |
                                      ((ull)h2 << 32) | ((ull)h3 << 48);
                *(ull*)(dl + 4 * q) = (ull)l0 | ((ull)l1 << 16) |
                                      ((ull)l2 << 32) | ((ull)l3 << 48);
            }
        }
#pragma unroll
        for (int q = 0; q < 4; q++) {
            const int v = tid + q * 256;
            const int sp = v >> 9;
            const int u = v & 511;
            const int r = u >> 2, seg = u & 3;
            const __nv_bfloat16* src =
                (sp ? Wl : Wh) + (size_t)(col0 + r) * K + ch * 32 + seg * 8;
            const uint32_t dst = (sp ? sbWl : sbWh) + r * 80 + seg * 16;
            CPASYNC16(dst, src);
        }
        asm volatile("cp.async.commit_group;" ::: "memory");
        asm volatile("cp.async.wait_group 0;" ::: "memory");
        __syncthreads();

#pragma unroll
        for (int s16 = 0; s16 < 2; s16++) {
            uint32_t bh[4][2], bl[4][2];
#pragma unroll
            for (int nt = 0; nt < 4; nt++) {
                const uint32_t ba = (wn * 32 + nt * 8 + g) * 80 + (s16 * 16 + 2 * tq) * 2;
                bh[nt][0] = *(const uint32_t*)((const char*)Ws_h + ba);
                bh[nt][1] = *(const uint32_t*)((const char*)Ws_h + ba + 16);
                bl[nt][0] = *(const uint32_t*)((const char*)Ws_l + ba);
                bl[nt][1] = *(const uint32_t*)((const char*)Ws_l + ba + 16);
            }
#pragma unroll
            for (int mt = 0; mt < 4; mt++) {
                const uint32_t ab = (uint32_t)((wm * 64 + mt * 16) * 80 + s16 * 32) + aoff;
                uint32_t ah[4], al[4];
                ldsm_x4(ah, sbAh + ab);
                ldsm_x4(al, sbAl + ab);
#pragma unroll
                for (int nt = 0; nt < 4; nt++) {
                    mma_bf16(c[mt][nt], ah, bh[nt]);
                    mma_bf16(c[mt][nt], al, bh[nt]);
                    mma_bf16(c[mt][nt], ah, bl[nt]);
                }
            }
        }
    }

#pragma unroll
    for (int nt = 0; nt < 4; nt++) {
        const int col = col0 + wn * 32 + nt * 8 + 2 * tq;
        const float2 bv = *(const float2*)(bias + col);
#pragma unroll
        for (int mt = 0; mt < 4; mt++) {
            const int r1 = row0 + wm * 64 + mt * 16 + g;
            *(float2*)&C[(size_t)r1 * G3 + col] =
                make_float2(c[mt][nt][0] + bv.x, c[mt][nt][1] + bv.y);
            *(float2*)&C[(size_t)(r1 + 8) * G3 + col] =
                make_float2(c[mt][nt][2] + bv.x, c[mt][nt][3] + bv.y);
        }
    }
}

// ---------------------------------------------------------------------------
// Transpose: in[R][C] -> out[C][R]
// ---------------------------------------------------------------------------
__global__ void transpose_kernel(const float* __restrict__ in,
                                 float* __restrict__ out, int R, int C)
{
    __shared__ float t[32][33];
    const int c0 = blockIdx.x * 32, r0 = blockIdx.y * 32;
    for (int j = threadIdx.y; j < 32; j += 8)
        t[j][threadIdx.x] = in[(size_t)(r0 + j) * C + c0 + threadIdx.x];
    __syncthreads();
    for (int j = threadIdx.y; j < 32; j += 8)
        out[(size_t)(c0 + j) * R + r0 + threadIdx.x] = t[threadIdx.x][j];
}

// ---------------------------------------------------------------------------
// Persistent GRU layer (R8 fp32 version — proven 3.2 ms/layer).
// 128 CTAs x 512 threads; h duplicated {h,h} in SMEM for fma.rn.f32x2;
// thread ng owns column pairs {2ng,2ng+1}+256p -> lane-contiguous Wt LDG.64.
// ---------------------------------------------------------------------------
#define RBM  16
#define RPAD 776
#define RTHREADS 512
#define REC_SMEM ((RBM * 512 + 2 * RBM * RPAD) * 4)   // 132096 bytes

__global__ __launch_bounds__(RTHREADS, 1) void gru_rec_kernel(
    const float* __restrict__ Wt,
    const float* __restrict__ bhh,
    const float* __restrict__ xw,
    float* __restrict__ ys,
    float* __restrict__ hout)
{
    extern __shared__ float sm[];
    float* h2_s = sm;
    float* G_s  = sm + RBM * 512;
    float* xw_s = G_s + RBM * RPAD;

    const int tid = threadIdx.x;
    const int n0 = blockIdx.x * RBM;

    const int ng = tid & 127;
    const int mg = tid >> 7;
    const int gm0 = mg * 4;
    const int nc0 = 2 * ng;
    const int qm = tid >> 5;
    const int qj = (tid & 31) << 3;

    for (int i = tid; i < RBM * 512; i += RTHREADS) h2_s[i] = 0.f;

    ull bh[3];
#pragma unroll
    for (int p = 0; p < 3; p++)
        bh[p] = *(const ull*)(bhh + nc0 + 256 * p);

    __syncthreads();

    for (int t = 0; t < TT; t++) {
#pragma unroll
        for (int c = 0; c < 6; c++) {
            const int v = tid + c * RTHREADS;
            const int rm = v / 192;
            const int c4 = v - rm * 192;
            const float* src = xw + ((size_t)(n0 + rm) * TT + t) * G3 + c4 * 4;
            unsigned dst = (unsigned)__cvta_generic_to_shared(
                xw_s + rm * RPAD + c4 * 4);
            CPASYNC16(dst, src);
        }
        asm volatile("cp.async.commit_group;" ::: "memory");

        ull acc[4][3];
#pragma unroll
        for (int i = 0; i < 4; i++) {
            acc[i][0] = bh[0]; acc[i][1] = bh[1]; acc[i][2] = bh[2];
        }
#pragma unroll 4
        for (int k = 0; k < HH; k++) {
            const float* wrow = Wt + (size_t)k * G3 + nc0;
            const ull w0 = *(const ull*)(wrow);
            const ull w1 = *(const ull*)(wrow + 256);
            const ull w2 = *(const ull*)(wrow + 512);
#pragma unroll
            for (int i = 0; i < 4; i++) {
                const ull hd = *(const ull*)&h2_s[(gm0 + i) * 512 + 2 * k];
                ffma2(acc[i][0], w0, hd);
                ffma2(acc[i][1], w1, hd);
                ffma2(acc[i][2], w2, hd);
            }
        }
#pragma unroll
        for (int i = 0; i < 4; i++) {
            float* grow = G_s + (gm0 + i) * RPAD + nc0;
#pragma unroll
            for (int p = 0; p < 3; p++) {
                float2 v = unpack2(acc[i][p]);
                *(float2*)(grow + 256 * p) = v;
            }
        }

        asm volatile("cp.async.wait_group 0;" ::: "memory");
        __syncthreads();

        const float* xr = xw_s + qm * RPAD;
        const float* gr = G_s + qm * RPAD;
        float* hrow = h2_s + qm * 512;
        float hn[8];
#pragma unroll
        for (int j = 0; j < 8; j++) {
            const int jj = qj + j;
            const float r = sigm_f(xr[jj] + gr[jj]);
            const float z = sigm_f(xr[HH + jj] + gr[HH + jj]);
            const float nv = tanh_f(xr[2 * HH + jj] + r * gr[2 * HH + jj]);
            const float hold = hrow[2 * jj];
            hn[j] = (1.f - z) * nv + z * hold;
            *(float2*)&hrow[2 * jj] = make_float2(hn[j], hn[j]);
        }
        if (ys) {
            float4* dst = (float4*)(ys + ((size_t)(n0 + qm) * TT + t) * HH + qj);
            dst[0] = make_float4(hn[0], hn[1], hn[2], hn[3]);
            dst[1] = make_float4(hn[4], hn[5], hn[6], hn[7]);
        }
        __syncthreads();
    }

    if (hout) {
        float* dst = hout + (size_t)(n0 + qm) * HH + qj;
        const float* hrow = h2_s + qm * 512;
        *(float4*)(dst)     = make_float4(hrow[2 * (qj + 0)], hrow[2 * (qj + 1)],
                                          hrow[2 * (qj + 2)], hrow[2 * (qj + 3)]);
        *(float4*)(dst + 4) = make_float4(hrow[2 * (qj + 4)], hrow[2 * (qj + 5)],
                                          hrow[2 * (qj + 6)], hrow[2 * (qj + 7)]);
    }
}

// ---------------------------------------------------------------------------
// gemm2 (fp32 f32x2) — MLP GEMM only
// ---------------------------------------------------------------------------
#define S2 258

__global__ __launch_bounds__(256, 2) void gemm2_kernel(
    const float* __restrict__ A,
    const float* __restrict__ Wt,
    const float* __restrict__ bias,
    float* __restrict__ C,
    int M, int Nn, int K)
{
    __shared__ float AsD[16 * S2];
    __shared__ float Ws[16 * 128];
    const int tid = threadIdx.x;
    const int row0 = blockIdx.y * 128;
    const int col0 = blockIdx.x * 128;
    const int ngrp = tid & 15, mgrp = tid >> 4;
    const int m0 = mgrp * 8;
    const int nc0 = 2 * ngrp;

    ull acc[8][4];
#pragma unroll
    for (int i = 0; i < 8; i++)
#pragma unroll
        for (int p = 0; p < 4; p++) acc[i][p] = 0ULL;

    for (int k0 = 0; k0 < K; k0 += 16) {
#pragma unroll
        for (int q = 0; q < 2; q++) {
            const int v = tid + q * 256;
            const int rm = v >> 2, kc = (v & 3) << 2;
            float4 av = *(const float4*)(A + (size_t)(row0 + rm) * K + k0 + kc);
            *(ull*)&AsD[(kc + 0) * S2 + 2 * rm] = dup2(av.x);
            *(ull*)&AsD[(kc + 1) * S2 + 2 * rm] = dup2(av.y);
            *(ull*)&AsD[(kc + 2) * S2 + 2 * rm] = dup2(av.z);
            *(ull*)&AsD[(kc + 3) * S2 + 2 * rm] = dup2(av.w);
            const int rk = v >> 5, nc = (v & 31) << 2;
            *(float4*)&Ws[rk * 128 + nc] =
                *(const float4*)(Wt + (size_t)(k0 + rk) * Nn + col0 + nc);
        }
        __syncthreads();
#pragma unroll
        for (int k = 0; k < 16; k++) {
            ull w[4];
#pragma unroll
            for (int p = 0; p < 4; p++)
                w[p] = *(const ull*)&Ws[k * 128 + nc0 + 32 * p];
#pragma unroll
            for (int i = 0; i < 8; i++) {
                ull ad = *(const ull*)&AsD[k * S2 + 2 * (m0 + i)];
#pragma unroll
                for (int p = 0; p < 4; p++) ffma2(acc[i][p], w[p], ad);
            }
        }
        __syncthreads();
    }

    float2 bp[4];
#pragma unroll
    for (int p = 0; p < 4; p++)
        bp[p] = *(const float2*)(bias + col0 + nc0 + 32 * p);
#pragma unroll
    for (int i = 0; i < 8; i++) {
        float* crow = C + (size_t)(row0 + m0 + i) * Nn + col0;
#pragma unroll
        for (int p = 0; p < 4; p++) {
            float2 v = unpack2(acc[i][p]);
            *(float2*)(crow + nc0 + 32 * p) =
                make_float2(v.x + bp[p].x, v.y + bp[p].y);
        }
    }
}

// ---------------------------------------------------------------------------
// Attention / tail kernels
// ---------------------------------------------------------------------------
__global__ void proj_kernel(const float* __restrict__ A, int M,
                            const float* __restrict__ Wm,
                            const float* __restrict__ bias,
                            float* __restrict__ out)
{
    const int head = blockIdx.z;
    const int col = blockIdx.x * 16 + threadIdx.x;
    const int row = blockIdx.y * 16 + threadIdx.y;
    const int rc = min(row, M - 1);
    const float* W = Wm + (size_t)head * HH * HD;
    __shared__ float As[16][17], Wsh[16][17];
    float acc = 0.f;
    for (int k0 = 0; k0 < HH; k0 += 16) {
        As[threadIdx.y][threadIdx.x] = A[(size_t)rc * HH + k0 + threadIdx.x];
        Wsh[threadIdx.y][threadIdx.x] = W[(size_t)(k0 + threadIdx.y) * HD + col];
        __syncthreads();
#pragma unroll
        for (int k = 0; k < 16; k++)
            acc += As[threadIdx.y][k] * Wsh[k][threadIdx.x];
        __syncthreads();
    }
    if (row < M)
        out[((size_t)head * M + row) * HD + col] = acc + bias[head * HD + col];
}

__global__ void attn1_kernel(const float* __restrict__ qh,
                             const float* __restrict__ kh,
                             const float* __restrict__ vh,
                             float* __restrict__ B)
{
    const int head = blockIdx.x / CC;
    const int l = blockIdx.x % CC;
    const int tid = threadIdx.x;
    __shared__ float p[NB];
    __shared__ float q[HD];
    __shared__ float red[256];
    if (tid < HD) q[tid] = qh[((size_t)head * CC + l) * HD + tid];
    __syncthreads();
    const float scale = 0.08838834764831845f;
    float lmax = -1e30f;
    for (int k = tid; k < NB; k += 256) {
        const float* kr = kh + ((size_t)head * NB + k) * HD;
        float s = 0.f;
#pragma unroll 4
        for (int d = 0; d < HD; d++) s += q[d] * kr[d];
        s *= scale;
        p[k] = s;
        lmax = fmaxf(lmax, s);
    }
    red[tid] = lmax; __syncthreads();
    for (int s = 128; s > 0; s >>= 1) {
        if (tid < s) red[tid] = fmaxf(red[tid], red[tid + s]);
        __syncthreads();
    }
    const float m = red[0];
    __syncthreads();
    float lsum = 0.f;
    for (int k = tid; k < NB; k += 256) {
        const float e = expf(p[k] - m);
        p[k] = e;
        lsum += e;
    }
    red[tid] = lsum; __syncthreads();
    for (int s = 128; s > 0; s >>= 1) {
        if (tid < s) red[tid] += red[tid + s];
        __syncthreads();
    }
    const float inv = 1.f / red[0];
    __syncthreads();
    const int col = tid & 127;
    const int half = tid >> 7;
    float o = 0.f;
    for (int k = half * 1024; k < half * 1024 + 1024; k++)
        o += p[k] * vh[((size_t)head * NB + k) * HD + col];
    red[tid] = o; __syncthreads();
    if (tid < HD)
        B[l * (NHD * HD) + head * HD + tid] = (red[tid] + red[tid + 128]) * inv;
}

__global__ void attn2_kernel(const float* __restrict__ qh,
                             const float* __restrict__ kh,
                             const float* __restrict__ vh,
                             float* __restrict__ Sp)
{
    const int l = blockIdx.x;
    const int head = blockIdx.y;
    const int tid = threadIdx.x;
    __shared__ float q[HD];
    __shared__ float sc[CC];
    q[tid] = qh[((size_t)head * NB + l) * HD + tid];
    __syncthreads();
    const float scale = 0.08838834764831845f;
    if (tid < CC) {
        const float* kr = kh + (head * CC + tid) * HD;
        float s = 0.f;
        for (int d = 0; d < HD; d++) s += q[d] * kr[d];
        sc[tid] = s * scale;
    }
    __syncthreads();
    float m = -1e30f;
#pragma unroll
    for (int k = 0; k < CC; k++) m = fmaxf(m, sc[k]);
    float sum = 0.f, o = 0.f;
#pragma unroll
    for (int k = 0; k < CC; k++) {
        const float e = expf(sc[k] - m);
        sum += e;
        o += e * vh[(head * CC + k) * HD + tid];
    }
    Sp[(size_t)l * HH + head * HD + tid] = o / sum;
}

__global__ void gate_mix_kernel(const float* __restrict__ S,
                                const float* __restrict__ Sp,
                                const float* __restrict__ Wg,
                                const float* __restrict__ bg,
                                float* __restrict__ Smix)
{
    __shared__ float red[256];
    const int l = blockIdx.x, d = threadIdx.x;
    const float sv = S[(size_t)l * HH + d];
    red[d] = sv * Wg[d];
    __syncthreads();
    for (int s = 128; s > 0; s >>= 1) {
        if (d < s) red[d] += red[d + s];
        __syncthreads();
    }
    const float alpha = 1.f / (1.f + expf(-(red[0] + bg[0])));
    Smix[(size_t)l * HH + d] = alpha * Sp[(size_t)l * HH + d] + (1.f - alpha) * sv;
}

__global__ void relu_add_kernel(const float* __restrict__ mlp,
                                float* __restrict__ Smix)
{
    const int idx = blockIdx.x * blockDim.x + threadIdx.x;
    Smix[idx] += fmaxf(mlp[idx], 0.f);
}

__global__ void rowdot_kernel(const float* __restrict__ S,
                              const float* __restrict__ W2,
                              const float* __restrict__ b2,
                              float* __restrict__ y)
{
    __shared__ float red[256];
    const int l = blockIdx.x, tid = threadIdx.x;
    red[tid] = S[(size_t)l * HH + tid] * W2[tid];
    __syncthreads();
    for (int s = 128; s > 0; s >>= 1) {
        if (tid < s) red[tid] += red[tid + s];
        __syncthreads();
    }
    if (tid == 0) y[l] = red[0] + b2[0];
}

__global__ void normalize_kernel(const float* __restrict__ y,
                                 float* __restrict__ out)
{
    __shared__ float red[1024];
    const int tid = threadIdx.x;
    const float a = y[tid], b = y[tid + 1024];
    red[tid] = a + b; __syncthreads();
    for (int s = 512; s > 0; s >>= 1) {
        if (tid < s) red[tid] += red[tid + s];
        __syncthreads();
    }
    const float mean = red[0] * (1.f / 2048.f);
    __syncthreads();
    const float da = a - mean, db = b - mean;
    red[tid] = da * da + db * db; __syncthreads();
    for (int s = 512; s > 0; s >>= 1) {
        if (tid < s) red[tid] += red[tid + s];
        __syncthreads();
    }
    const float inv = 1.f / (sqrtf(red[0] / 2047.f) + 1e-8f);
    out[tid] = da * inv;
    out[tid + 1024] = db * inv;
}

// ---------------------------------------------------------------------------
// Host driver — default stream, graph-capturable.
// ---------------------------------------------------------------------------
extern "C" void kernel_launch(void* const* d_in, const int* in_sizes, int n_in,
                              void* d_out, int out_size)
{
    const float* x      = (const float*)d_in[0];
    const float* W_ih0  = (const float*)d_in[1];
    const float* W_hh0  = (const float*)d_in[2];
    const float* b_ih0  = (const float*)d_in[3];
    const float* b_hh0  = (const float*)d_in[4];
    const float* W_ih1  = (const float*)d_in[5];
    const float* W_hh1  = (const float*)d_in[6];
    const float* b_ih1  = (const float*)d_in[7];
    const float* b_hh1  = (const float*)d_in[8];
    const float* Wq     = (const float*)d_in[9];
    const float* bq     = (const float*)d_in[10];
    const float* Wk     = (const float*)d_in[11];
    const float* bk     = (const float*)d_in[12];
    const float* Wv     = (const float*)d_in[13];
    const float* bv     = (const float*)d_in[14];
    const float* R      = (const float*)d_in[15];
    const float* W_gate = (const float*)d_in[16];
    const float* b_gate = (const float*)d_in[17];
    const float* W1     = (const float*)d_in[18];
    const float* b1     = (const float*)d_in[19];
    const float* W2     = (const float*)d_in[20];
    const float* b2     = (const float*)d_in[21];
    float* out = (float*)d_out;

    float *xw, *ys0, *S, *wt_hh0, *wt_hh1, *wt_w1, *wqkv, *bqkv, *qkv;
    __nv_bfloat16 *wih0_h, *wih0_l, *wih1_h, *wih1_l;
    float *qh1, *Bb, *kh2, *vh2, *Sp, *Smix, *mlp, *yraw;
    cudaGetSymbolAddress((void**)&xw, g_xw);
    cudaGetSymbolAddress((void**)&ys0, g_ys0);
    cudaGetSymbolAddress((void**)&S, g_S);
    cudaGetSymbolAddress((void**)&wt_hh0, g_wt_hh0);
    cudaGetSymbolAddress((void**)&wt_hh1, g_wt_hh1);
    cudaGetSymbolAddress((void**)&wt_w1, g_wt_w1);
    cudaGetSymbolAddress((void**)&wih0_h, g_wih0_h);
    cudaGetSymbolAddress((void**)&wih0_l, g_wih0_l);
    cudaGetSymbolAddress((void**)&wih1_h, g_wih1_h);
    cudaGetSymbolAddress((void**)&wih1_l, g_wih1_l);
    cudaGetSymbolAddress((void**)&wqkv, g_wqkv);
    cudaGetSymbolAddress((void**)&bqkv, g_bqkv);
    cudaGetSymbolAddress((void**)&qkv, g_qkv);
    cudaGetSymbolAddress((void**)&qh1, g_qh1);
    cudaGetSymbolAddress((void**)&Bb, g_B);
    cudaGetSymbolAddress((void**)&kh2, g_kh2);
    cudaGetSymbolAddress((void**)&vh2, g_vh2);
    cudaGetSymbolAddress((void**)&Sp, g_Sp);
    cudaGetSymbolAddress((void**)&Smix, g_Smix);
    cudaGetSymbolAddress((void**)&mlp, g_mlp);
    cudaGetSymbolAddress((void**)&yraw, g_yraw);

    cudaFuncSetAttribute(gru_rec_kernel,
                         cudaFuncAttributeMaxDynamicSharedMemorySize, REC_SMEM);

    const dim3 blk2(16, 16);
    const dim3 tb(32, 8);

    // [0] split W_ih0, [1] transpose W_hh0
    split_w_kernel<<<(G3 * INDIM + 255) / 256, 256>>>(W_ih0, wih0_h, wih0_l, G3 * INDIM);
    transpose_kernel<<<dim3(HH / 32, G3 / 32), tb>>>(W_hh0, wt_hh0, G3, HH);
    // [2] xW0 (HMMA), [3] rec0 (fp32) -- ncu window lands ~here
    gemm_hmma_kernel<<<dim3(G3 / 128, NTROWS / 128), 256>>>(
        x, wih0_h, wih0_l, b_ih0, xw, INDIM);
    gru_rec_kernel<<<NB / RBM, RTHREADS, REC_SMEM>>>(
        wt_hh0, b_hh0, xw, ys0, nullptr);

    // [4] split W_ih1, [5] xW1 (HMMA), [6] transpose W_hh1, [7] rec1
    split_w_kernel<<<(G3 * HH + 255) / 256, 256>>>(W_ih1, wih1_h, wih1_l, G3 * HH);
    gemm_hmma_kernel<<<dim3(G3 / 128, NTROWS / 128), 256>>>(
        ys0, wih1_h, wih1_l, b_ih1, xw, HH);
    transpose_kernel<<<dim3(HH / 32, G3 / 32), tb>>>(W_hh1, wt_hh1, G3, HH);
    gru_rec_kernel<<<NB / RBM, RTHREADS, REC_SMEM>>>(
        wt_hh1, b_hh1, xw, nullptr, S);

    // Pack QKV weights; one fused projection for all S-based heads (z=6)
    pack_qkv_kernel<<<(6 * HH * HD + 255) / 256, 256>>>(
        Wq, Wk, Wv, bq, bk, bv, wqkv, bqkv);
    proj_kernel<<<dim3(8, NB / 16, 6), blk2>>>(S, NB, wqkv, bqkv, qkv);
    float* qh2 = qkv;                       // slots 0,1
    float* kh1 = qkv + 2 * (size_t)NB * HD; // slots 2,3
    float* vh1 = qkv + 4 * (size_t)NB * HD; // slots 4,5

    // Small projections + attention
    proj_kernel<<<dim3(8, 2, NHD), blk2>>>(R, CC, Wq, bq, qh1);
    attn1_kernel<<<NHD * CC, 256>>>(qh1, kh1, vh1, Bb);
    proj_kernel<<<dim3(8, 2, NHD), blk2>>>(Bb, CC, Wk, bk, kh2);
    proj_kernel<<<dim3(8, 2, NHD), blk2>>>(Bb, CC, Wv, bv, vh2);
    attn2_kernel<<<dim3(NB, NHD), 128>>>(qh2, kh2, vh2, Sp);

    // Gate mix + MLP + output
    transpose_kernel<<<dim3(HH / 32, HH / 32), tb>>>(W1, wt_w1, HH, HH);
    gate_mix_kernel<<<NB, 256>>>(S, Sp, W_gate, b_gate, Smix);
    gemm2_kernel<<<dim3(HH / 128, NB / 128), 256>>>(
        Smix, wt_w1, b1, mlp, NB, HH, HH);
    relu_add_kernel<<<(NB * HH) / 256, 256>>>(mlp, Smix);
    rowdot_kernel<<<NB, 256>>>(Smix, W2, b2, yraw);
    normalize_kernel<<<1, 1024>>>(yraw, out);
}